// round 16
// baseline (speedup 1.0000x reference)
#include <cuda_runtime.h>

// BrockHommes: B=8192 rows, T=4096 strictly-sequential steps, one row per
// thread, grid=256 x block=32 (solo warp per SMSP; co-residency proven bad).
//
// The per-step stream is hand-scheduled for IN-ORDER issue (R10/R11 evidence:
// ptxas respects this order and every instruction before a chain op delays it):
//   ex2 x3            (MUFU rt 8: issue 0,8,16)
//   m0..m3, esr       (5 instrs fill the p1/p2 arrival gap)
//   den adds          (issue as p1/p2/p3 land)
//   rcp               (fires ~@38, rd ~@55)
//   E1..E3, num chain (inside rcp shadow)
//   U' = fma(num, rd, esr);  XT = fma(num, rd, ES)
//   B_k = fmin(U'*E_k, 88)   (tail is issue-bound: fewest instrs wins,
//                             so R10's nE/w distribution is reverted)
// ~26 instrs, ~70 cyc simulated step.
//
// Algebra (exact up to fp rounding):
//  * softmax shift-invariance, regime-0 shift: p_0 = 1, p_k = 2^(U*E'_k),
//    E'_k = bl*(d_k - d_0) = bgd_k*x3 + bcd_k,  U = x1 - R*x2,
//    bl = beta*log2e absorbed into E' constants.
//  * overflow guard: fmin(.,88) (load-bearing for saturated rows).
//  * x_t = num*rd + es;  U_next = num*rd + esr,  esr = fma(-R, x1, es).

#define B_CONST 8192
#define T_CONST 4096

__device__ __forceinline__ float ex2a(float x){float y;asm("ex2.approx.f32 %0, %1;":"=f"(y):"f"(x));return y;}
__device__ __forceinline__ float rcpa(float x){float y;asm("rcp.approx.f32 %0, %1;":"=f"(y):"f"(x));return y;}

// One step. In: A1..A3 = clamped exponents (carried); X1,X2; ES = eps*sigma/R.
// Out: XT = x_t; B1..B3 = next step's clamped exponents.
#define BH_STEP(ES, X1, X2, A1,A2,A3, XT, B1,B2,B3) \
  { \
    /* MUFU head */ \
    float p1 = ex2a(A1); \
    float p2 = ex2a(A2); \
    float p3 = ex2a(A3); \
    /* fill the p-arrival gap (5 instrs) */ \
    float m0 = fmaf(gi0, X1, bi0); \
    float m1 = fmaf(gi1, X1, bi1); \
    float m2 = fmaf(gi2, X1, bi2); \
    float m3 = fmaf(gi3, X1, bi3); \
    float esr = fmaf(nR, X1, ES); \
    /* den adds issue as p's land; rcp immediately after */ \
    float den = ((1.0f + p1) + p2) + p3; \
    float rd = rcpa(den); \
    /* rcp shadow */ \
    float E1 = fmaf(bgd1, X2, bcd1); \
    float E2 = fmaf(bgd2, X2, bcd2); \
    float E3 = fmaf(bgd3, X2, bcd3); \
    float num = fmaf(p3, m3, fmaf(p2, m2, fmaf(p1, m1, m0))); \
    /* tail: close the recurrence with minimal instruction count */ \
    float Un = fmaf(num, rd, esr); \
    XT = fmaf(num, rd, ES); \
    B1 = fminf(Un * E1, 88.0f); \
    B2 = fminf(Un * E2, 88.0f); \
    B3 = fminf(Un * E3, 88.0f); \
  }

__global__ void __launch_bounds__(32, 1)
bh_kernel(const float* __restrict__ theta,
          const float* __restrict__ eps,
          float* __restrict__ out)
{
    const int b = blockIdx.x * 32 + threadIdx.x;   // 0..8191

    const float* th = theta + (size_t)b * 11;
    const float L2E = 1.44269504088896340736f;

    const float g0 = th[1], g1 = th[2], g2 = th[3], g3 = th[4];
    const float c0 = th[5], c1 = th[6], c2 = th[7], c3 = th[8];
    const float R    = 1.0f + th[10];
    const float iR   = 1.0f / R;                  // one-time accurate div
    const float bl   = th[0] * L2E;               // beta * log2(e)
    const float nR   = -R;
    const float sg   = th[9] * iR;                // sigma / R
    const float gi0 = g0 * iR, gi1 = g1 * iR, gi2 = g2 * iR, gi3 = g3 * iR;
    const float bi0 = c0 * iR, bi1 = c1 * iR, bi2 = c2 * iR, bi3 = c3 * iR;
    const float bgd1 = bl * (g1 - g0), bgd2 = bl * (g2 - g0), bgd3 = bl * (g3 - g0);
    const float bcd1 = bl * (c1 - c0), bcd2 = bl * (c2 - c0), bcd3 = bl * (c3 - c0);

    const float4* ep4 = reinterpret_cast<const float4*>(eps + (size_t)b * T_CONST);
    float4*       o4  = reinterpret_cast<float4*>(out + (size_t)b * T_CONST);
    const int T8 = T_CONST / 8;                   // 8 steps per outer iter

    // carried state; t=0: x1=x2=0 -> U=0 -> A_k = 0 (p_k = 1).
    float x1 = 0.f, x2 = 0.f;
    float A1 = 0.f, A2 = 0.f, A3 = 0.f;

    // prefetch 16 steps ahead (two float4 per outer iter)
    float4 pfA0 = ep4[0], pfA1 = ep4[1];
    float4 pfB0 = ep4[2], pfB1 = ep4[3];

    for (int i = 0; i < T8; ++i) {
        float4 evA = pfA0, evB = pfA1;
        pfA0 = pfB0; pfA1 = pfB1;
        int nidx = (2 * i + 4 < 2 * T8) ? (2 * i + 4) : (2 * T8 - 2);
        pfB0 = ep4[nidx];
        pfB1 = ep4[nidx + 1];

        float es0 = evA.x * sg, es1 = evA.y * sg, es2 = evA.z * sg, es3 = evA.w * sg;
        float es4 = evB.x * sg, es5 = evB.y * sg, es6 = evB.z * sg, es7 = evB.w * sg;

        float xt0, xt1, xt2, xt3, xt4, xt5, xt6, xt7;
        float Ab1,Ab2,Ab3, Ac1,Ac2,Ac3, Ad1,Ad2,Ad3, Ae1,Ae2,Ae3;
        float Af1,Af2,Af3, Ag1,Ag2,Ag3, Ah1,Ah2,Ah3;

        BH_STEP(es0, x1,  x2,  A1,A2,A3,    xt0, Ab1,Ab2,Ab3);
        BH_STEP(es1, xt0, x1,  Ab1,Ab2,Ab3, xt1, Ac1,Ac2,Ac3);
        BH_STEP(es2, xt1, xt0, Ac1,Ac2,Ac3, xt2, Ad1,Ad2,Ad3);
        BH_STEP(es3, xt2, xt1, Ad1,Ad2,Ad3, xt3, Ae1,Ae2,Ae3);
        BH_STEP(es4, xt3, xt2, Ae1,Ae2,Ae3, xt4, Af1,Af2,Af3);
        BH_STEP(es5, xt4, xt3, Af1,Af2,Af3, xt5, Ag1,Ag2,Ag3);
        BH_STEP(es6, xt5, xt4, Ag1,Ag2,Ag3, xt6, Ah1,Ah2,Ah3);
        BH_STEP(es7, xt6, xt5, Ah1,Ah2,Ah3, xt7, A1,A2,A3);

        x2 = xt6;
        x1 = xt7;

        o4[2 * i]     = make_float4(xt0, xt1, xt2, xt3);
        o4[2 * i + 1] = make_float4(xt4, xt5, xt6, xt7);
    }
}

extern "C" void kernel_launch(void* const* d_in, const int* in_sizes, int n_in,
                              void* d_out, int out_size)
{
    const float* theta = (const float*)d_in[0];   // (B, 11) float32
    const float* eps   = (const float*)d_in[1];   // (B, T)  float32
    float*       out   = (float*)d_out;           // (B, T)  float32

    bh_kernel<<<B_CONST / 32, 32>>>(theta, eps, out);
}